// round 1
// baseline (speedup 1.0000x reference)
#include <cuda_runtime.h>
#include <cuda_bf16.h>
#include <math_constants.h>

// Problem constants
#define TT   2048      // tgt/src len
#define BB   4         // batch
#define DD   256       // embed dim
#define HH   8         // heads
#define HD   32        // head dim
#define RR   (TT*BB)   // 8192 rows
#define SCALE_Q 0.17677669529663687f   // 32^-0.5

// Scratch (device globals: allocation-free per harness rules)
__device__ float g_qp[RR * DD];
__device__ float g_kp[RR * DD];
__device__ float g_vp[RR * DD];
__device__ float g_ao[RR * DD];

// ---------------------------------------------------------------------------
// Projection GEMM: Y[r,n] = alpha * sum_k X[r,k]*W[n,k] + bias[n]
// M=8192, N=256, K=256. Block tile 64x64, 256 threads, 4x4 microtile.
// ---------------------------------------------------------------------------
__global__ __launch_bounds__(256)
void proj_kernel(const float* __restrict__ X, const float* __restrict__ W,
                 const float* __restrict__ bias, float* __restrict__ Y,
                 float alpha) {
    __shared__ __align__(16) float As[64][16];
    __shared__ __align__(16) float Bs[16][68];

    const int tid = threadIdx.x;
    const int m0  = blockIdx.x * 64;
    const int n0  = blockIdx.y * 64;
    const int tx  = tid & 15;        // 0..15 -> n micro
    const int ty  = tid >> 4;        // 0..15 -> m micro
    const int lrow = tid >> 2;       // 0..63 (load row)
    const int lcol = (tid & 3) * 4;  // 0,4,8,12 (load col, k-dir)

    float acc[4][4];
#pragma unroll
    for (int i = 0; i < 4; i++)
#pragma unroll
        for (int j = 0; j < 4; j++) acc[i][j] = 0.0f;

    for (int k0 = 0; k0 < DD; k0 += 16) {
        // A tile: X[m0+lrow][k0+lcol..+3]
        float4 a4 = *(const float4*)&X[(m0 + lrow) * DD + k0 + lcol];
        *(float4*)&As[lrow][lcol] = a4;
        // B tile: W[n0+lrow][k0+lcol..+3] stored transposed Bs[k][n]
        float4 b4 = *(const float4*)&W[(n0 + lrow) * DD + k0 + lcol];
        Bs[lcol + 0][lrow] = b4.x;
        Bs[lcol + 1][lrow] = b4.y;
        Bs[lcol + 2][lrow] = b4.z;
        Bs[lcol + 3][lrow] = b4.w;
        __syncthreads();

#pragma unroll
        for (int k = 0; k < 16; k++) {
            float a0 = As[ty * 4 + 0][k];
            float a1 = As[ty * 4 + 1][k];
            float a2 = As[ty * 4 + 2][k];
            float a3 = As[ty * 4 + 3][k];
            float4 b = *(const float4*)&Bs[k][tx * 4];
            acc[0][0] += a0 * b.x; acc[0][1] += a0 * b.y; acc[0][2] += a0 * b.z; acc[0][3] += a0 * b.w;
            acc[1][0] += a1 * b.x; acc[1][1] += a1 * b.y; acc[1][2] += a1 * b.z; acc[1][3] += a1 * b.w;
            acc[2][0] += a2 * b.x; acc[2][1] += a2 * b.y; acc[2][2] += a2 * b.z; acc[2][3] += a2 * b.w;
            acc[3][0] += a3 * b.x; acc[3][1] += a3 * b.y; acc[3][2] += a3 * b.z; acc[3][3] += a3 * b.w;
        }
        __syncthreads();
    }

    const int n = n0 + tx * 4;
    float4 bb = *(const float4*)&bias[n];
#pragma unroll
    for (int i = 0; i < 4; i++) {
        float4 o;
        o.x = alpha * acc[i][0] + bb.x;
        o.y = alpha * acc[i][1] + bb.y;
        o.z = alpha * acc[i][2] + bb.z;
        o.w = alpha * acc[i][3] + bb.w;
        *(float4*)&Y[(m0 + ty * 4 + i) * DD + n] = o;
    }
}

// ---------------------------------------------------------------------------
// Flash attention: one block per (head, 64-query tile). 128 threads.
// Thread t owns query q=t/2 and d-half (t&1)*16. Redundant row stats per pair.
// ---------------------------------------------------------------------------
__global__ __launch_bounds__(128)
void attn_kernel() {
    const int bh  = blockIdx.y;      // 0..31 = b*H + h
    const int b   = bh >> 3;
    const int h   = bh & 7;
    const int tq0 = blockIdx.x * 64;
    const int tid = threadIdx.x;
    const int q   = tid >> 1;        // 0..63 local query
    const int dh  = tid & 1;
    const int d0  = dh * 16;

    __shared__ __align__(16) float Ks[64][32];
    __shared__ __align__(16) float Vs[64][32];
    __shared__ float Ss[64][65];     // padded: stride 65 avoids bank conflicts

    // Q row -> registers
    float qreg[32];
    {
        const int t = tq0 + q;
        const float4* src = (const float4*)&g_qp[(t * BB + b) * DD + h * HD];
#pragma unroll
        for (int i = 0; i < 8; i++) {
            float4 v4 = src[i];
            qreg[4 * i + 0] = v4.x; qreg[4 * i + 1] = v4.y;
            qreg[4 * i + 2] = v4.z; qreg[4 * i + 3] = v4.w;
        }
    }

    float4 acc[4];
#pragma unroll
    for (int v = 0; v < 4; v++) acc[v] = make_float4(0.f, 0.f, 0.f, 0.f);
    float m = -CUDART_INF_F;
    float l = 0.0f;

    for (int kt = 0; kt < TT / 64; kt++) {
        const int tk0 = kt * 64;
        // Load K,V tiles (64x32 each); 512 float4 total, 4 per thread
#pragma unroll
        for (int i = 0; i < 4; i++) {
            int idx = tid + 128 * i;            // 0..511
            int row = idx >> 3;
            int c4  = (idx & 7) * 4;
            long off = (long)((tk0 + row) * BB + b) * DD + h * HD + c4;
            *(float4*)&Ks[row][c4] = *(const float4*)&g_kp[off];
            *(float4*)&Vs[row][c4] = *(const float4*)&g_vp[off];
        }
        __syncthreads();

        // Scores: thread computes its query's dot with 32 keys (its j-half)
#pragma unroll 4
        for (int jj = 0; jj < 32; jj++) {
            int j = dh * 32 + jj;
            const float4* kr = (const float4*)&Ks[j][0];
            float s = 0.0f;
#pragma unroll
            for (int c = 0; c < 8; c++) {
                float4 kk = kr[c];
                s += qreg[4 * c + 0] * kk.x;
                s += qreg[4 * c + 1] * kk.y;
                s += qreg[4 * c + 2] * kk.z;
                s += qreg[4 * c + 3] * kk.w;
            }
            Ss[q][j] = s;
        }
        __syncthreads();

        // Online softmax update (both threads of a pair compute identical stats)
        float mt = m;
#pragma unroll 8
        for (int j = 0; j < 64; j++) mt = fmaxf(mt, Ss[q][j]);
        float corr = __expf(m - mt);   // first tile: exp(-inf)=0
        l *= corr;
#pragma unroll
        for (int v = 0; v < 4; v++) {
            acc[v].x *= corr; acc[v].y *= corr; acc[v].z *= corr; acc[v].w *= corr;
        }
#pragma unroll 4
        for (int j = 0; j < 64; j++) {
            float p = __expf(Ss[q][j] - mt);
            l += p;
            const float4* vr = (const float4*)&Vs[j][d0];
#pragma unroll
            for (int v = 0; v < 4; v++) {
                float4 vv = vr[v];
                acc[v].x += p * vv.x; acc[v].y += p * vv.y;
                acc[v].z += p * vv.z; acc[v].w += p * vv.w;
            }
        }
        m = mt;
        __syncthreads();
    }

    const float inv = 1.0f / l;
    const int t = tq0 + q;
    float* dst = &g_ao[(t * BB + b) * DD + h * HD + d0];
#pragma unroll
    for (int v = 0; v < 4; v++) {
        float4 o;
        o.x = acc[v].x * inv; o.y = acc[v].y * inv;
        o.z = acc[v].z * inv; o.w = acc[v].w * inv;
        *(float4*)&dst[v * 4] = o;
    }
}

// ---------------------------------------------------------------------------
extern "C" void kernel_launch(void* const* d_in, const int* in_sizes, int n_in,
                              void* d_out, int out_size) {
    const float* q  = (const float*)d_in[0];
    const float* k  = (const float*)d_in[1];
    const float* v  = (const float*)d_in[2];
    const float* Wq = (const float*)d_in[3];
    const float* bq = (const float*)d_in[4];
    const float* Wk = (const float*)d_in[5];
    const float* bk = (const float*)d_in[6];
    const float* Wv = (const float*)d_in[7];
    const float* bv = (const float*)d_in[8];
    const float* Wp = (const float*)d_in[9];
    const float* bp = (const float*)d_in[10];
    float* out = (float*)d_out;

    float *qp, *kp, *vp, *ao;
    cudaGetSymbolAddress((void**)&qp, g_qp);
    cudaGetSymbolAddress((void**)&kp, g_kp);
    cudaGetSymbolAddress((void**)&vp, g_vp);
    cudaGetSymbolAddress((void**)&ao, g_ao);

    dim3 pgrid(RR / 64, DD / 64);
    proj_kernel<<<pgrid, 256>>>(q, Wq, bq, qp, SCALE_Q);
    proj_kernel<<<pgrid, 256>>>(k, Wk, bk, kp, 1.0f);
    proj_kernel<<<pgrid, 256>>>(v, Wv, bv, vp, 1.0f);

    dim3 agrid(TT / 64, BB * HH);
    attn_kernel<<<agrid, 128>>>();

    proj_kernel<<<pgrid, 256>>>(ao, Wp, bp, out, 1.0f);
}

// round 2
// speedup vs baseline: 3.5403x; 3.5403x over previous
#include <cuda_runtime.h>
#include <cuda_bf16.h>
#include <math_constants.h>
#include <cstdint>

// Problem constants
#define TT   2048      // tgt/src len
#define BB   4         // batch
#define DD   256       // embed dim
#define HH   8         // heads
#define HD   32        // head dim
#define RR   (TT*BB)   // 8192 rows
#define SCALE_Q 0.17677669529663687f   // 32^-0.5

// Scratch (device globals: allocation-free per harness rules)
__device__ float g_qp[RR * DD];
__device__ float g_kp[RR * DD];
__device__ float g_vp[RR * DD];
__device__ float g_ao[RR * DD];

// ---------------------------------------------------------------------------
// Projection GEMM: Y[r,n] = alpha * sum_k X[r,k]*W[n,k] + bias[n]
// M=8192, N=256, K=256. Block tile 64x64, 256 threads, 4x4 microtile.
// ---------------------------------------------------------------------------
__global__ __launch_bounds__(256)
void proj_kernel(const float* __restrict__ X, const float* __restrict__ W,
                 const float* __restrict__ bias, float* __restrict__ Y,
                 float alpha) {
    __shared__ __align__(16) float As[64][16];
    __shared__ __align__(16) float Bs[16][68];

    const int tid = threadIdx.x;
    const int m0  = blockIdx.x * 64;
    const int n0  = blockIdx.y * 64;
    const int tx  = tid & 15;
    const int ty  = tid >> 4;
    const int lrow = tid >> 2;
    const int lcol = (tid & 3) * 4;

    float acc[4][4];
#pragma unroll
    for (int i = 0; i < 4; i++)
#pragma unroll
        for (int j = 0; j < 4; j++) acc[i][j] = 0.0f;

    for (int k0 = 0; k0 < DD; k0 += 16) {
        float4 a4 = *(const float4*)&X[(m0 + lrow) * DD + k0 + lcol];
        *(float4*)&As[lrow][lcol] = a4;
        float4 b4 = *(const float4*)&W[(n0 + lrow) * DD + k0 + lcol];
        Bs[lcol + 0][lrow] = b4.x;
        Bs[lcol + 1][lrow] = b4.y;
        Bs[lcol + 2][lrow] = b4.z;
        Bs[lcol + 3][lrow] = b4.w;
        __syncthreads();

#pragma unroll
        for (int k = 0; k < 16; k++) {
            float a0 = As[ty * 4 + 0][k];
            float a1 = As[ty * 4 + 1][k];
            float a2 = As[ty * 4 + 2][k];
            float a3 = As[ty * 4 + 3][k];
            float4 b = *(const float4*)&Bs[k][tx * 4];
            acc[0][0] += a0 * b.x; acc[0][1] += a0 * b.y; acc[0][2] += a0 * b.z; acc[0][3] += a0 * b.w;
            acc[1][0] += a1 * b.x; acc[1][1] += a1 * b.y; acc[1][2] += a1 * b.z; acc[1][3] += a1 * b.w;
            acc[2][0] += a2 * b.x; acc[2][1] += a2 * b.y; acc[2][2] += a2 * b.z; acc[2][3] += a2 * b.w;
            acc[3][0] += a3 * b.x; acc[3][1] += a3 * b.y; acc[3][2] += a3 * b.z; acc[3][3] += a3 * b.w;
        }
        __syncthreads();
    }

    const int n = n0 + tx * 4;
    float4 bb = *(const float4*)&bias[n];
#pragma unroll
    for (int i = 0; i < 4; i++) {
        float4 o;
        o.x = alpha * acc[i][0] + bb.x;
        o.y = alpha * acc[i][1] + bb.y;
        o.z = alpha * acc[i][2] + bb.z;
        o.w = alpha * acc[i][3] + bb.w;
        *(float4*)&Y[(m0 + ty * 4 + i) * DD + n] = o;
    }
}

// ---------------------------------------------------------------------------
// tf32 mma.sync m16n8k8 wrapper (raw fp32 bits as tf32 operands)
// ---------------------------------------------------------------------------
__device__ __forceinline__ void mma_tf32(float& d0, float& d1, float& d2, float& d3,
                                         float a0, float a1, float a2, float a3,
                                         float b0, float b1) {
    uint32_t ua0 = __float_as_uint(a0), ua1 = __float_as_uint(a1);
    uint32_t ua2 = __float_as_uint(a2), ua3 = __float_as_uint(a3);
    uint32_t ub0 = __float_as_uint(b0), ub1 = __float_as_uint(b1);
    asm volatile(
        "mma.sync.aligned.m16n8k8.row.col.f32.tf32.tf32.f32 "
        "{%0,%1,%2,%3}, {%4,%5,%6,%7}, {%8,%9}, {%0,%1,%2,%3};"
        : "+f"(d0), "+f"(d1), "+f"(d2), "+f"(d3)
        : "r"(ua0), "r"(ua1), "r"(ua2), "r"(ua3), "r"(ub0), "r"(ub1));
}

// ---------------------------------------------------------------------------
// Tensor-core flash attention.
// Block: 128 threads (4 warps), 64 queries. Warp owns 16 queries.
// K-tile = 64 keys. Scores/P live in mma fragments; key columns permuted
// (kappa) so score C-fragments directly serve as PV A-fragments.
// ---------------------------------------------------------------------------
#define KSTRIDE 36
#define VSTRIDE 68

__global__ __launch_bounds__(128)
void attn_tc_kernel() {
    const int bh   = blockIdx.y;
    const int b    = bh >> 3;
    const int h    = bh & 7;
    const int tq0  = blockIdx.x * 64;
    const int tid  = threadIdx.x;
    const int warp = tid >> 5;
    const int lane = tid & 31;
    const int g    = lane >> 2;      // groupID 0..7
    const int t    = lane & 3;       // threadID_in_group
    const int kappa = (g >> 1) + (g & 1) * 4;   // key-column permutation

    __shared__ __align__(16) float Ks[64][KSTRIDE];   // [key][dim]
    __shared__ __align__(16) float VsT[32][VSTRIDE];  // [dim][key]

    // Queries owned by this thread's fragments
    const int r0 = tq0 + warp * 16 + g;   // row for c0/c1 (a0/a2)
    const int r1 = r0 + 8;                // row for c2/c3 (a1/a3)

    // Q A-fragments: qa[kc] = {a0,a1,a2,a3} for dim-chunk kc (8 dims each)
    float qa[4][4];
    {
        const float* q0p = &g_qp[(r0 * BB + b) * DD + h * HD];
        const float* q1p = &g_qp[(r1 * BB + b) * DD + h * HD];
#pragma unroll
        for (int kc = 0; kc < 4; kc++) {
            qa[kc][0] = q0p[kc * 8 + t];
            qa[kc][1] = q1p[kc * 8 + t];
            qa[kc][2] = q0p[kc * 8 + t + 4];
            qa[kc][3] = q1p[kc * 8 + t + 4];
        }
    }

    // Output accumulators: o[dt] = C-fragment for dim-tile dt (8 dims)
    float o[4][4];
#pragma unroll
    for (int dt = 0; dt < 4; dt++)
#pragma unroll
        for (int i = 0; i < 4; i++) o[dt][i] = 0.0f;
    float m0 = -CUDART_INF_F, m1 = -CUDART_INF_F;
    float l0 = 0.0f, l1 = 0.0f;

    for (int kt = 0; kt < TT / 64; kt++) {
        const int tk0 = kt * 64;
        __syncthreads();   // protect smem from previous iteration's readers
        // Load K (row-major, stride 36) and V (transposed, stride 68)
#pragma unroll
        for (int i = 0; i < 4; i++) {
            int idx = tid + 128 * i;          // 0..511
            int row = idx >> 3;               // key 0..63
            int c4  = (idx & 7) * 4;          // dim 0,4,..28
            int off = ((tk0 + row) * BB + b) * DD + h * HD + c4;
            float4 kk = *(const float4*)&g_kp[off];
            *(float4*)&Ks[row][c4] = kk;
            float4 vv = *(const float4*)&g_vp[off];
            VsT[c4 + 0][row] = vv.x;
            VsT[c4 + 1][row] = vv.y;
            VsT[c4 + 2][row] = vv.z;
            VsT[c4 + 3][row] = vv.w;
        }
        __syncthreads();

        // Scores: s[nt] = C-frag of Q(16x32) @ K^T for 8 permuted keys
        float s[8][4];
#pragma unroll
        for (int nt = 0; nt < 8; nt++) {
            s[nt][0] = s[nt][1] = s[nt][2] = s[nt][3] = 0.0f;
            const float* kr = &Ks[nt * 8 + kappa][0];
#pragma unroll
            for (int kc = 0; kc < 4; kc++) {
                mma_tf32(s[nt][0], s[nt][1], s[nt][2], s[nt][3],
                         qa[kc][0], qa[kc][1], qa[kc][2], qa[kc][3],
                         kr[kc * 8 + t], kr[kc * 8 + t + 4]);
            }
        }

        // Row max (rows r0: regs 0,1; r1: regs 2,3)
        float mx0 = s[0][0], mx1 = s[0][2];
#pragma unroll
        for (int nt = 0; nt < 8; nt++) {
            mx0 = fmaxf(mx0, fmaxf(s[nt][0], s[nt][1]));
            mx1 = fmaxf(mx1, fmaxf(s[nt][2], s[nt][3]));
        }
        mx0 = fmaxf(mx0, __shfl_xor_sync(0xffffffff, mx0, 1));
        mx0 = fmaxf(mx0, __shfl_xor_sync(0xffffffff, mx0, 2));
        mx1 = fmaxf(mx1, __shfl_xor_sync(0xffffffff, mx1, 1));
        mx1 = fmaxf(mx1, __shfl_xor_sync(0xffffffff, mx1, 2));

        float mn0 = fmaxf(m0, mx0);
        float mn1 = fmaxf(m1, mx1);
        float corr0 = __expf(m0 - mn0);   // 0 on first tile
        float corr1 = __expf(m1 - mn1);
        m0 = mn0; m1 = mn1;
#pragma unroll
        for (int dt = 0; dt < 4; dt++) {
            o[dt][0] *= corr0; o[dt][1] *= corr0;
            o[dt][2] *= corr1; o[dt][3] *= corr1;
        }
        l0 *= corr0; l1 *= corr1;

        // exp + row sums (in fragment registers)
        float ls0 = 0.0f, ls1 = 0.0f;
#pragma unroll
        for (int nt = 0; nt < 8; nt++) {
            s[nt][0] = __expf(s[nt][0] - mn0);
            s[nt][1] = __expf(s[nt][1] - mn0);
            s[nt][2] = __expf(s[nt][2] - mn1);
            s[nt][3] = __expf(s[nt][3] - mn1);
            ls0 += s[nt][0] + s[nt][1];
            ls1 += s[nt][2] + s[nt][3];
        }
        ls0 += __shfl_xor_sync(0xffffffff, ls0, 1);
        ls0 += __shfl_xor_sync(0xffffffff, ls0, 2);
        ls1 += __shfl_xor_sync(0xffffffff, ls1, 1);
        ls1 += __shfl_xor_sync(0xffffffff, ls1, 2);
        l0 += ls0; l1 += ls1;

        // P @ V : score C-frags (c0,c2,c1,c3) == PV A-frags (a0,a1,a2,a3)
        // thanks to the kappa key permutation.
#pragma unroll
        for (int dt = 0; dt < 4; dt++) {
            const float* vr = &VsT[dt * 8 + g][0];
#pragma unroll
            for (int kc = 0; kc < 8; kc++) {
                mma_tf32(o[dt][0], o[dt][1], o[dt][2], o[dt][3],
                         s[kc][0], s[kc][2], s[kc][1], s[kc][3],
                         vr[kc * 8 + t], vr[kc * 8 + t + 4]);
            }
        }
    }

    // Epilogue: normalize and store (c0,c1 = adjacent cols -> float2)
    const float inv0 = 1.0f / l0;
    const float inv1 = 1.0f / l1;
    float* d0p = &g_ao[(r0 * BB + b) * DD + h * HD];
    float* d1p = &g_ao[(r1 * BB + b) * DD + h * HD];
#pragma unroll
    for (int dt = 0; dt < 4; dt++) {
        int col = dt * 8 + 2 * t;
        float2 w0; w0.x = o[dt][0] * inv0; w0.y = o[dt][1] * inv0;
        float2 w1; w1.x = o[dt][2] * inv1; w1.y = o[dt][3] * inv1;
        *(float2*)&d0p[col] = w0;
        *(float2*)&d1p[col] = w1;
    }
}

// ---------------------------------------------------------------------------
extern "C" void kernel_launch(void* const* d_in, const int* in_sizes, int n_in,
                              void* d_out, int out_size) {
    const float* q  = (const float*)d_in[0];
    const float* k  = (const float*)d_in[1];
    const float* v  = (const float*)d_in[2];
    const float* Wq = (const float*)d_in[3];
    const float* bq = (const float*)d_in[4];
    const float* Wk = (const float*)d_in[5];
    const float* bk = (const float*)d_in[6];
    const float* Wv = (const float*)d_in[7];
    const float* bv = (const float*)d_in[8];
    const float* Wp = (const float*)d_in[9];
    const float* bp = (const float*)d_in[10];
    float* out = (float*)d_out;

    float *qp, *kp, *vp, *ao;
    cudaGetSymbolAddress((void**)&qp, g_qp);
    cudaGetSymbolAddress((void**)&kp, g_kp);
    cudaGetSymbolAddress((void**)&vp, g_vp);
    cudaGetSymbolAddress((void**)&ao, g_ao);

    dim3 pgrid(RR / 64, DD / 64);
    proj_kernel<<<pgrid, 256>>>(q, Wq, bq, qp, SCALE_Q);
    proj_kernel<<<pgrid, 256>>>(k, Wk, bk, kp, 1.0f);
    proj_kernel<<<pgrid, 256>>>(v, Wv, bv, vp, 1.0f);

    dim3 agrid(TT / 64, BB * HH);
    attn_tc_kernel<<<agrid, 128>>>();

    proj_kernel<<<pgrid, 256>>>(ao, Wp, bp, out, 1.0f);
}

// round 3
// speedup vs baseline: 4.1852x; 1.1822x over previous
#include <cuda_runtime.h>
#include <cuda_bf16.h>
#include <math_constants.h>
#include <cstdint>

// Problem constants
#define TT   2048      // tgt/src len
#define BB   4         // batch
#define DD   256       // embed dim
#define HH   8         // heads
#define HD   32        // head dim
#define RR   (TT*BB)   // 8192 rows
#define SCALE_Q 0.17677669529663687f   // 32^-0.5

// Scratch (device globals: allocation-free per harness rules)
__device__ float g_qp[RR * DD];
__device__ float g_kp[RR * DD];
__device__ float g_vp[RR * DD];
__device__ float g_ao[RR * DD];

// ---------------------------------------------------------------------------
// tf32 helpers
// ---------------------------------------------------------------------------
__device__ __forceinline__ uint32_t f2tf32(float x) {
    uint32_t r;
    asm("cvt.rna.tf32.f32 %0, %1;" : "=r"(r) : "f"(x));
    return r;
}

// mma with raw uint operands
__device__ __forceinline__ void mma_u(float& d0, float& d1, float& d2, float& d3,
                                      uint32_t a0, uint32_t a1, uint32_t a2, uint32_t a3,
                                      uint32_t b0, uint32_t b1) {
    asm volatile(
        "mma.sync.aligned.m16n8k8.row.col.f32.tf32.tf32.f32 "
        "{%0,%1,%2,%3}, {%4,%5,%6,%7}, {%8,%9}, {%0,%1,%2,%3};"
        : "+f"(d0), "+f"(d1), "+f"(d2), "+f"(d3)
        : "r"(a0), "r"(a1), "r"(a2), "r"(a3), "r"(b0), "r"(b1));
}

// fp32-operand wrapper (single tf32 pass) for attention
__device__ __forceinline__ void mma_tf32(float& d0, float& d1, float& d2, float& d3,
                                         float a0, float a1, float a2, float a3,
                                         float b0, float b1) {
    mma_u(d0, d1, d2, d3,
          __float_as_uint(a0), __float_as_uint(a1),
          __float_as_uint(a2), __float_as_uint(a3),
          __float_as_uint(b0), __float_as_uint(b1));
}

// ---------------------------------------------------------------------------
// Tensor-core projection GEMM (3xTF32: fp32-grade accuracy)
// Y[r,n] = alpha * sum_k X[r,k]*W[n,k] + bias[n];  M=8192, N=256, K=256
// Block tile 128x64, 8 warps (256 thr); warp = 16 rows x 64 cols.
// Smem stride 36 -> all fragment LDS bank-conflict-free.
// ---------------------------------------------------------------------------
struct ProjArg {
    const float* X; const float* W; const float* B; float* Y; float alpha;
};

#define PSTR 36

__global__ __launch_bounds__(256)
void proj_tc_kernel(ProjArg p0, ProjArg p1, ProjArg p2) {
    const ProjArg p = (blockIdx.z == 0) ? p0 : (blockIdx.z == 1) ? p1 : p2;

    __shared__ __align__(16) float Xs[128][PSTR];
    __shared__ __align__(16) float Ws[64][PSTR];

    const int tid  = threadIdx.x;
    const int warp = tid >> 5;
    const int lane = tid & 31;
    const int g    = lane >> 2;
    const int t    = lane & 3;
    const int m0   = blockIdx.x * 128;
    const int n0   = blockIdx.y * 64;

    float acc[8][4];
#pragma unroll
    for (int nt = 0; nt < 8; nt++)
#pragma unroll
        for (int i = 0; i < 4; i++) acc[nt][i] = 0.0f;

    const int lrow = tid >> 3;        // 0..31
    const int lc4  = (tid & 7) * 4;   // 0,4,...,28

    for (int k0 = 0; k0 < DD; k0 += 32) {
        // X tile: 128 rows x 32 cols (4 float4 per thread)
#pragma unroll
        for (int i = 0; i < 4; i++) {
            int row = lrow + 32 * i;
            float4 v4 = *(const float4*)&p.X[(m0 + row) * DD + k0 + lc4];
            *(float4*)&Xs[row][lc4] = v4;
        }
        // W tile: 64 rows x 32 cols (2 float4 per thread)
#pragma unroll
        for (int i = 0; i < 2; i++) {
            int row = lrow + 32 * i;
            float4 v4 = *(const float4*)&p.W[(n0 + row) * DD + k0 + lc4];
            *(float4*)&Ws[row][lc4] = v4;
        }
        __syncthreads();

#pragma unroll
        for (int kk = 0; kk < 4; kk++) {
            // A fragment (rows warp*16+g, +8; cols kk*8+t, +4), hi/lo split
            float af[4];
            af[0] = Xs[warp * 16 + g    ][kk * 8 + t];
            af[1] = Xs[warp * 16 + g + 8][kk * 8 + t];
            af[2] = Xs[warp * 16 + g    ][kk * 8 + t + 4];
            af[3] = Xs[warp * 16 + g + 8][kk * 8 + t + 4];
            uint32_t ah[4], al[4];
#pragma unroll
            for (int i = 0; i < 4; i++) {
                ah[i] = f2tf32(af[i]);
                al[i] = f2tf32(af[i] - __uint_as_float(ah[i]));
            }
#pragma unroll
            for (int nt = 0; nt < 8; nt++) {
                float b0 = Ws[nt * 8 + g][kk * 8 + t];
                float b1 = Ws[nt * 8 + g][kk * 8 + t + 4];
                uint32_t bh0 = f2tf32(b0);
                uint32_t bl0 = f2tf32(b0 - __uint_as_float(bh0));
                uint32_t bh1 = f2tf32(b1);
                uint32_t bl1 = f2tf32(b1 - __uint_as_float(bh1));
                // 3xTF32: hi*hi + hi*lo + lo*hi
                mma_u(acc[nt][0], acc[nt][1], acc[nt][2], acc[nt][3],
                      ah[0], ah[1], ah[2], ah[3], bl0, bl1);
                mma_u(acc[nt][0], acc[nt][1], acc[nt][2], acc[nt][3],
                      al[0], al[1], al[2], al[3], bh0, bh1);
                mma_u(acc[nt][0], acc[nt][1], acc[nt][2], acc[nt][3],
                      ah[0], ah[1], ah[2], ah[3], bh0, bh1);
            }
        }
        __syncthreads();
    }

    // Epilogue: C frag c0=C[g][2t], c1=C[g][2t+1], c2=C[g+8][2t], c3=C[g+8][2t+1]
    const int r0 = m0 + warp * 16 + g;
    const int r1 = r0 + 8;
    const float alpha = p.alpha;
#pragma unroll
    for (int nt = 0; nt < 8; nt++) {
        int col = n0 + nt * 8 + 2 * t;
        float bx = p.B[col], by = p.B[col + 1];
        float2 w0, w1;
        w0.x = alpha * acc[nt][0] + bx; w0.y = alpha * acc[nt][1] + by;
        w1.x = alpha * acc[nt][2] + bx; w1.y = alpha * acc[nt][3] + by;
        *(float2*)&p.Y[r0 * DD + col] = w0;
        *(float2*)&p.Y[r1 * DD + col] = w1;
    }
}

// ---------------------------------------------------------------------------
// Tensor-core flash attention (unchanged from R2).
// Block: 128 threads (4 warps), 64 queries. Warp owns 16 queries.
// ---------------------------------------------------------------------------
#define KSTRIDE 36
#define VSTRIDE 68

__global__ __launch_bounds__(128)
void attn_tc_kernel() {
    const int bh   = blockIdx.y;
    const int b    = bh >> 3;
    const int h    = bh & 7;
    const int tq0  = blockIdx.x * 64;
    const int tid  = threadIdx.x;
    const int warp = tid >> 5;
    const int lane = tid & 31;
    const int g    = lane >> 2;
    const int t    = lane & 3;
    const int kappa = (g >> 1) + (g & 1) * 4;

    __shared__ __align__(16) float Ks[64][KSTRIDE];
    __shared__ __align__(16) float VsT[32][VSTRIDE];

    const int r0 = tq0 + warp * 16 + g;
    const int r1 = r0 + 8;

    float qa[4][4];
    {
        const float* q0p = &g_qp[(r0 * BB + b) * DD + h * HD];
        const float* q1p = &g_qp[(r1 * BB + b) * DD + h * HD];
#pragma unroll
        for (int kc = 0; kc < 4; kc++) {
            qa[kc][0] = q0p[kc * 8 + t];
            qa[kc][1] = q1p[kc * 8 + t];
            qa[kc][2] = q0p[kc * 8 + t + 4];
            qa[kc][3] = q1p[kc * 8 + t + 4];
        }
    }

    float o[4][4];
#pragma unroll
    for (int dt = 0; dt < 4; dt++)
#pragma unroll
        for (int i = 0; i < 4; i++) o[dt][i] = 0.0f;
    float m0 = -CUDART_INF_F, m1 = -CUDART_INF_F;
    float l0 = 0.0f, l1 = 0.0f;

    for (int kt = 0; kt < TT / 64; kt++) {
        const int tk0 = kt * 64;
        __syncthreads();
#pragma unroll
        for (int i = 0; i < 4; i++) {
            int idx = tid + 128 * i;
            int row = idx >> 3;
            int c4  = (idx & 7) * 4;
            int off = ((tk0 + row) * BB + b) * DD + h * HD + c4;
            float4 kk = *(const float4*)&g_kp[off];
            *(float4*)&Ks[row][c4] = kk;
            float4 vv = *(const float4*)&g_vp[off];
            VsT[c4 + 0][row] = vv.x;
            VsT[c4 + 1][row] = vv.y;
            VsT[c4 + 2][row] = vv.z;
            VsT[c4 + 3][row] = vv.w;
        }
        __syncthreads();

        float s[8][4];
#pragma unroll
        for (int nt = 0; nt < 8; nt++) {
            s[nt][0] = s[nt][1] = s[nt][2] = s[nt][3] = 0.0f;
            const float* kr = &Ks[nt * 8 + kappa][0];
#pragma unroll
            for (int kc = 0; kc < 4; kc++) {
                mma_tf32(s[nt][0], s[nt][1], s[nt][2], s[nt][3],
                         qa[kc][0], qa[kc][1], qa[kc][2], qa[kc][3],
                         kr[kc * 8 + t], kr[kc * 8 + t + 4]);
            }
        }

        float mx0 = s[0][0], mx1 = s[0][2];
#pragma unroll
        for (int nt = 0; nt < 8; nt++) {
            mx0 = fmaxf(mx0, fmaxf(s[nt][0], s[nt][1]));
            mx1 = fmaxf(mx1, fmaxf(s[nt][2], s[nt][3]));
        }
        mx0 = fmaxf(mx0, __shfl_xor_sync(0xffffffff, mx0, 1));
        mx0 = fmaxf(mx0, __shfl_xor_sync(0xffffffff, mx0, 2));
        mx1 = fmaxf(mx1, __shfl_xor_sync(0xffffffff, mx1, 1));
        mx1 = fmaxf(mx1, __shfl_xor_sync(0xffffffff, mx1, 2));

        float mn0 = fmaxf(m0, mx0);
        float mn1 = fmaxf(m1, mx1);
        float corr0 = __expf(m0 - mn0);
        float corr1 = __expf(m1 - mn1);
        m0 = mn0; m1 = mn1;
#pragma unroll
        for (int dt = 0; dt < 4; dt++) {
            o[dt][0] *= corr0; o[dt][1] *= corr0;
            o[dt][2] *= corr1; o[dt][3] *= corr1;
        }
        l0 *= corr0; l1 *= corr1;

        float ls0 = 0.0f, ls1 = 0.0f;
#pragma unroll
        for (int nt = 0; nt < 8; nt++) {
            s[nt][0] = __expf(s[nt][0] - mn0);
            s[nt][1] = __expf(s[nt][1] - mn0);
            s[nt][2] = __expf(s[nt][2] - mn1);
            s[nt][3] = __expf(s[nt][3] - mn1);
            ls0 += s[nt][0] + s[nt][1];
            ls1 += s[nt][2] + s[nt][3];
        }
        ls0 += __shfl_xor_sync(0xffffffff, ls0, 1);
        ls0 += __shfl_xor_sync(0xffffffff, ls0, 2);
        ls1 += __shfl_xor_sync(0xffffffff, ls1, 1);
        ls1 += __shfl_xor_sync(0xffffffff, ls1, 2);
        l0 += ls0; l1 += ls1;

#pragma unroll
        for (int dt = 0; dt < 4; dt++) {
            const float* vr = &VsT[dt * 8 + g][0];
#pragma unroll
            for (int kc = 0; kc < 8; kc++) {
                mma_tf32(o[dt][0], o[dt][1], o[dt][2], o[dt][3],
                         s[kc][0], s[kc][2], s[kc][1], s[kc][3],
                         vr[kc * 8 + t], vr[kc * 8 + t + 4]);
            }
        }
    }

    const float inv0 = 1.0f / l0;
    const float inv1 = 1.0f / l1;
    float* d0p = &g_ao[(r0 * BB + b) * DD + h * HD];
    float* d1p = &g_ao[(r1 * BB + b) * DD + h * HD];
#pragma unroll
    for (int dt = 0; dt < 4; dt++) {
        int col = dt * 8 + 2 * t;
        float2 w0; w0.x = o[dt][0] * inv0; w0.y = o[dt][1] * inv0;
        float2 w1; w1.x = o[dt][2] * inv1; w1.y = o[dt][3] * inv1;
        *(float2*)&d0p[col] = w0;
        *(float2*)&d1p[col] = w1;
    }
}

// ---------------------------------------------------------------------------
extern "C" void kernel_launch(void* const* d_in, const int* in_sizes, int n_in,
                              void* d_out, int out_size) {
    const float* q  = (const float*)d_in[0];
    const float* k  = (const float*)d_in[1];
    const float* v  = (const float*)d_in[2];
    const float* Wq = (const float*)d_in[3];
    const float* bq = (const float*)d_in[4];
    const float* Wk = (const float*)d_in[5];
    const float* bk = (const float*)d_in[6];
    const float* Wv = (const float*)d_in[7];
    const float* bv = (const float*)d_in[8];
    const float* Wp = (const float*)d_in[9];
    const float* bp = (const float*)d_in[10];
    float* out = (float*)d_out;

    float *qp, *kp, *vp, *ao;
    cudaGetSymbolAddress((void**)&qp, g_qp);
    cudaGetSymbolAddress((void**)&kp, g_kp);
    cudaGetSymbolAddress((void**)&vp, g_vp);
    cudaGetSymbolAddress((void**)&ao, g_ao);

    ProjArg pq = {q, Wq, bq, qp, SCALE_Q};
    ProjArg pk = {k, Wk, bk, kp, 1.0f};
    ProjArg pv = {v, Wv, bv, vp, 1.0f};
    ProjArg po = {ao, Wp, bp, out, 1.0f};

    dim3 pgrid(RR / 128, DD / 64, 3);
    proj_tc_kernel<<<pgrid, 256>>>(pq, pk, pv);

    dim3 agrid(TT / 64, BB * HH);
    attn_tc_kernel<<<agrid, 128>>>();

    dim3 ogrid(RR / 128, DD / 64, 1);
    proj_tc_kernel<<<ogrid, 256>>>(po, po, po);
}